// round 1
// baseline (speedup 1.0000x reference)
#include <cuda_runtime.h>
#include <math.h>

#define H 1024
#define F 2048
#define E 8
#define T 2048

#define BM 64
#define BN 64
#define BK 16

// ---- scratch (device globals: allocation-free per harness rules) ----
__device__ int   g_cnt[E];
__device__ int   g_tok[E * T];
__device__ float g_wgt[E * T];
__device__ float g_mid[(size_t)E * T * F];   // [E][T][F] compacted per-expert rows

// ---------------------------------------------------------------
__global__ void zero_cnt_kernel() {
    if (threadIdx.x < E) g_cnt[threadIdx.x] = 0;
}

// ---------------------------------------------------------------
// One block (128 threads) per token: logits, softmax-top2, scatter.
__global__ __launch_bounds__(128) void router_kernel(
    const float* __restrict__ x, const float* __restrict__ gw,
    float* __restrict__ logits_out)
{
    const int t   = blockIdx.x;
    const int tid = threadIdx.x;
    const float* xr = x + (size_t)t * H;

    float acc[E];
#pragma unroll
    for (int e = 0; e < E; e++) acc[e] = 0.f;

    for (int h = tid; h < H; h += 128) {
        float xv = xr[h];
#pragma unroll
        for (int e = 0; e < E; e++) acc[e] += xv * gw[e * H + h];
    }
#pragma unroll
    for (int e = 0; e < E; e++) {
#pragma unroll
        for (int o = 16; o > 0; o >>= 1)
            acc[e] += __shfl_xor_sync(0xffffffffu, acc[e], o);
    }

    __shared__ float s[4][E];
    int warp = tid >> 5, lane = tid & 31;
    if (lane == 0) {
#pragma unroll
        for (int e = 0; e < E; e++) s[warp][e] = acc[e];
    }
    __syncthreads();

    if (tid == 0) {
        float l[E];
#pragma unroll
        for (int e = 0; e < E; e++) l[e] = s[0][e] + s[1][e] + s[2][e] + s[3][e];
        if (logits_out) {
#pragma unroll
            for (int e = 0; e < E; e++) logits_out[(size_t)t * E + e] = l[e];
        }
        // top-2 (ties: lower index first, matching jax top_k)
        int i1 = 0;
#pragma unroll
        for (int e = 1; e < E; e++) if (l[e] > l[i1]) i1 = e;
        int i2 = -1;
#pragma unroll
        for (int e = 0; e < E; e++) {
            if (e == i1) continue;
            if (i2 < 0 || l[e] > l[i2]) i2 = e;
        }
        // renormalized top-2 softmax weights: w1 = 1/(1+exp(l2-l1))
        float wa = 1.f / (1.f + expf(l[i2] - l[i1]));
        float wb = 1.f - wa;
        int s1 = atomicAdd(&g_cnt[i1], 1);
        g_tok[i1 * T + s1] = t; g_wgt[i1 * T + s1] = wa;
        int s2 = atomicAdd(&g_cnt[i2], 1);
        g_tok[i2 * T + s2] = t; g_wgt[i2 * T + s2] = wb;
    }
}

// ---------------------------------------------------------------
// GEMM1: for expert e, rows = gathered tokens:
//   mid[m, n] = silu(x_m . w1[e,n,:]) * (x_m . w3[e,n,:]),  n in [0,F)
__global__ __launch_bounds__(256) void gemm1_kernel(
    const float* __restrict__ x,
    const float* __restrict__ w1,
    const float* __restrict__ w3)
{
    const int e  = blockIdx.z;
    const int n0 = blockIdx.x * BN;
    const int m0 = blockIdx.y * BM;
    const int ne = g_cnt[e];
    if (m0 >= ne) return;

    __shared__ float As [BK][BM];
    __shared__ float Bs1[BK][BN];
    __shared__ float Bs3[BK][BN];

    const int tid = threadIdx.x;
    const int tx  = tid & 15;       // 0..15 -> 4 cols each
    const int ty  = tid >> 4;       // 0..15 -> 4 rows each

    // loader mapping: each thread loads a float4 along k
    const int lr = tid >> 2;        // 0..63 row within tile
    const int lk = (tid & 3) << 2;  // 0,4,8,12

    const int am  = m0 + lr;
    const int tok = (am < ne) ? g_tok[e * T + am] : g_tok[e * T];
    const float* xrow  = x  + (size_t)tok * H;
    const float* w1row = w1 + ((size_t)e * F + n0 + lr) * H;
    const float* w3row = w3 + ((size_t)e * F + n0 + lr) * H;

    float acc1[4][4] = {}, acc3[4][4] = {};

    for (int k0 = 0; k0 < H; k0 += BK) {
        float4 av  = *(const float4*)(xrow  + k0 + lk);
        float4 b1v = *(const float4*)(w1row + k0 + lk);
        float4 b3v = *(const float4*)(w3row + k0 + lk);
        __syncthreads();
        As [lk + 0][lr] = av.x;  As [lk + 1][lr] = av.y;
        As [lk + 2][lr] = av.z;  As [lk + 3][lr] = av.w;
        Bs1[lk + 0][lr] = b1v.x; Bs1[lk + 1][lr] = b1v.y;
        Bs1[lk + 2][lr] = b1v.z; Bs1[lk + 3][lr] = b1v.w;
        Bs3[lk + 0][lr] = b3v.x; Bs3[lk + 1][lr] = b3v.y;
        Bs3[lk + 2][lr] = b3v.z; Bs3[lk + 3][lr] = b3v.w;
        __syncthreads();

#pragma unroll
        for (int kk = 0; kk < BK; kk++) {
            float4 a  = *(const float4*)&As [kk][ty * 4];
            float4 b1 = *(const float4*)&Bs1[kk][tx * 4];
            float4 b3 = *(const float4*)&Bs3[kk][tx * 4];
            float ar[4] = {a.x, a.y, a.z, a.w};
            float b1r[4] = {b1.x, b1.y, b1.z, b1.w};
            float b3r[4] = {b3.x, b3.y, b3.z, b3.w};
#pragma unroll
            for (int i = 0; i < 4; i++)
#pragma unroll
                for (int j = 0; j < 4; j++) {
                    acc1[i][j] += ar[i] * b1r[j];
                    acc3[i][j] += ar[i] * b3r[j];
                }
        }
    }

#pragma unroll
    for (int i = 0; i < 4; i++) {
        int m = m0 + ty * 4 + i;
        if (m >= ne) continue;
        float* dst = g_mid + ((size_t)e * T + m) * F + n0 + tx * 4;
        float4 v;
        float hh, gg;
        hh = acc1[i][0]; gg = acc3[i][0]; v.x = hh / (1.f + expf(-hh)) * gg;
        hh = acc1[i][1]; gg = acc3[i][1]; v.y = hh / (1.f + expf(-hh)) * gg;
        hh = acc1[i][2]; gg = acc3[i][2]; v.z = hh / (1.f + expf(-hh)) * gg;
        hh = acc1[i][3]; gg = acc3[i][3]; v.w = hh / (1.f + expf(-hh)) * gg;
        *(float4*)dst = v;
    }
}

// ---------------------------------------------------------------
// GEMM2: out[token, n] += weight * ( mid[m,:] . w2[e,n,:] ), n in [0,H)
__global__ __launch_bounds__(256) void gemm2_kernel(
    const float* __restrict__ w2,
    float* __restrict__ out)
{
    const int e  = blockIdx.z;
    const int n0 = blockIdx.x * BN;
    const int m0 = blockIdx.y * BM;
    const int ne = g_cnt[e];
    if (m0 >= ne) return;

    __shared__ float As[BK][BM];
    __shared__ float Bs[BK][BN];

    const int tid = threadIdx.x;
    const int tx  = tid & 15;
    const int ty  = tid >> 4;

    const int lr = tid >> 2;
    const int lk = (tid & 3) << 2;

    const float* arow = g_mid + ((size_t)e * T + m0 + lr) * F;
    const float* brow = w2 + ((size_t)e * H + n0 + lr) * F;

    float acc[4][4] = {};

    for (int k0 = 0; k0 < F; k0 += BK) {
        float4 av = *(const float4*)(arow + k0 + lk);
        float4 bv = *(const float4*)(brow + k0 + lk);
        __syncthreads();
        As[lk + 0][lr] = av.x; As[lk + 1][lr] = av.y;
        As[lk + 2][lr] = av.z; As[lk + 3][lr] = av.w;
        Bs[lk + 0][lr] = bv.x; Bs[lk + 1][lr] = bv.y;
        Bs[lk + 2][lr] = bv.z; Bs[lk + 3][lr] = bv.w;
        __syncthreads();

#pragma unroll
        for (int kk = 0; kk < BK; kk++) {
            float4 a = *(const float4*)&As[kk][ty * 4];
            float4 b = *(const float4*)&Bs[kk][tx * 4];
            float ar[4] = {a.x, a.y, a.z, a.w};
            float br[4] = {b.x, b.y, b.z, b.w};
#pragma unroll
            for (int i = 0; i < 4; i++)
#pragma unroll
                for (int j = 0; j < 4; j++)
                    acc[i][j] += ar[i] * br[j];
        }
    }

#pragma unroll
    for (int i = 0; i < 4; i++) {
        int m = m0 + ty * 4 + i;
        if (m >= ne) continue;
        int   tok = g_tok[e * T + m];
        float w   = g_wgt[e * T + m];
        float* dst = out + (size_t)tok * H + n0 + tx * 4;
        atomicAdd(dst + 0, w * acc[i][0]);
        atomicAdd(dst + 1, w * acc[i][1]);
        atomicAdd(dst + 2, w * acc[i][2]);
        atomicAdd(dst + 3, w * acc[i][3]);
    }
}

// ---------------------------------------------------------------
extern "C" void kernel_launch(void* const* d_in, const int* in_sizes, int n_in,
                              void* d_out, int out_size)
{
    const float* x  = (const float*)d_in[0];   // [B,S,H] fp32
    const float* gw = (const float*)d_in[1];   // [E,H]
    const float* w1 = (const float*)d_in[2];   // [E,F,H]
    const float* w2 = (const float*)d_in[3];   // [E,H,F]
    const float* w3 = (const float*)d_in[4];   // [E,F,H]
    float* out = (float*)d_out;

    const size_t main_sz = (size_t)T * H;      // 2,097,152
    float* logits = ((size_t)out_size >= main_sz + (size_t)T * E)
                        ? out + main_sz : nullptr;

    // zero everything (out region accumulated via atomics; poisoned 0xAA otherwise)
    cudaMemsetAsync(d_out, 0, (size_t)out_size * sizeof(float));
    zero_cnt_kernel<<<1, 32>>>();
    router_kernel<<<T, 128>>>(x, gw, logits);
    gemm1_kernel<<<dim3(F / BN, T / BM, E), 256>>>(x, w1, w3);
    gemm2_kernel<<<dim3(H / BN, T / BM, E), 256>>>(w2, out);
}

// round 2
// speedup vs baseline: 2.8509x; 2.8509x over previous
#include <cuda_runtime.h>
#include <math.h>

#define H 1024
#define F 2048
#define E 8
#define T 2048

#define BM 128
#define BN 64
#define BK 16
#define SP 20            // padded smem stride (words): (20m+k)%32 bijective -> conflict-free

// ---- scratch (device globals: allocation-free per harness rules) ----
__device__ int   g_cnt[E];
__device__ int   g_tok[E * T];
__device__ float g_wgt[E * T];
__device__ float g_mid[(size_t)E * T * F];   // [E][T][F] compacted per-expert rows

// ---------------------------------------------------------------
__device__ __forceinline__ unsigned f2tf(float f) {
    unsigned u;
    asm("cvt.rna.tf32.f32 %0, %1;" : "=r"(u) : "f"(f));
    return u;
}
__device__ __forceinline__ uint4 f4_to_tf(float4 v) {
    uint4 r;
    r.x = f2tf(v.x); r.y = f2tf(v.y); r.z = f2tf(v.z); r.w = f2tf(v.w);
    return r;
}
__device__ __forceinline__ void mma_tf32(float c[4], const unsigned a[4], const unsigned b[2]) {
    asm volatile(
        "mma.sync.aligned.m16n8k8.row.col.f32.tf32.tf32.f32 "
        "{%0,%1,%2,%3}, {%4,%5,%6,%7}, {%8,%9}, {%0,%1,%2,%3};"
        : "+f"(c[0]), "+f"(c[1]), "+f"(c[2]), "+f"(c[3])
        : "r"(a[0]), "r"(a[1]), "r"(a[2]), "r"(a[3]), "r"(b[0]), "r"(b[1]));
}

// ---------------------------------------------------------------
__global__ void zero_cnt_kernel() {
    if (threadIdx.x < E) g_cnt[threadIdx.x] = 0;
}

// ---------------------------------------------------------------
// One block (128 threads) per token: logits, softmax-top2, scatter.
__global__ __launch_bounds__(128) void router_kernel(
    const float* __restrict__ x, const float* __restrict__ gw,
    float* __restrict__ logits_out)
{
    const int t   = blockIdx.x;
    const int tid = threadIdx.x;
    const float* xr = x + (size_t)t * H;

    float acc[E];
#pragma unroll
    for (int e = 0; e < E; e++) acc[e] = 0.f;

    for (int h = tid; h < H; h += 128) {
        float xv = xr[h];
#pragma unroll
        for (int e = 0; e < E; e++) acc[e] += xv * gw[e * H + h];
    }
#pragma unroll
    for (int e = 0; e < E; e++) {
#pragma unroll
        for (int o = 16; o > 0; o >>= 1)
            acc[e] += __shfl_xor_sync(0xffffffffu, acc[e], o);
    }

    __shared__ float s[4][E];
    int warp = tid >> 5, lane = tid & 31;
    if (lane == 0) {
#pragma unroll
        for (int e = 0; e < E; e++) s[warp][e] = acc[e];
    }
    __syncthreads();

    if (tid == 0) {
        float l[E];
#pragma unroll
        for (int e = 0; e < E; e++) l[e] = s[0][e] + s[1][e] + s[2][e] + s[3][e];
        if (logits_out) {
#pragma unroll
            for (int e = 0; e < E; e++) logits_out[(size_t)t * E + e] = l[e];
        }
        int i1 = 0;
#pragma unroll
        for (int e = 1; e < E; e++) if (l[e] > l[i1]) i1 = e;
        int i2 = -1;
#pragma unroll
        for (int e = 0; e < E; e++) {
            if (e == i1) continue;
            if (i2 < 0 || l[e] > l[i2]) i2 = e;
        }
        float wa = 1.f / (1.f + expf(l[i2] - l[i1]));
        float wb = 1.f - wa;
        int s1 = atomicAdd(&g_cnt[i1], 1);
        g_tok[i1 * T + s1] = t; g_wgt[i1 * T + s1] = wa;
        int s2 = atomicAdd(&g_cnt[i2], 1);
        g_tok[i2 * T + s2] = t; g_wgt[i2 * T + s2] = wb;
    }
}

// ---------------------------------------------------------------
// GEMM1 (tf32 tensor cores): mid = silu(x.w1^T) * (x.w3^T), gathered rows.
// Block: 128(M) x 64(N), 256 thr = 8 warps (4x2), warp 32x32, mma m16n8k8.
__global__ __launch_bounds__(256, 2) void gemm1_kernel(
    const float* __restrict__ x,
    const float* __restrict__ w1,
    const float* __restrict__ w3)
{
    const int e  = blockIdx.z;
    const int n0 = blockIdx.x * BN;
    const int m0 = blockIdx.y * BM;
    const int ne = g_cnt[e];
    if (m0 >= ne) return;

    __shared__ unsigned As [BM * SP];
    __shared__ unsigned Bs1[BN * SP];
    __shared__ unsigned Bs3[BN * SP];

    const int tid = threadIdx.x;

    // ---- loader mapping ----
    const int c4   = tid & 3;          // float4 index along k
    const int ar0  = tid >> 2;         // A rows: ar0 and ar0+64
    const int ar1  = ar0 + 64;
    const int br   = tid >> 2;         // B row 0..63

    const int ma0 = m0 + ar0, ma1 = m0 + ar1;
    const int tk0 = (ma0 < ne) ? g_tok[e * T + ma0] : g_tok[e * T];
    const int tk1 = (ma1 < ne) ? g_tok[e * T + ma1] : g_tok[e * T];
    const float* ap0 = x + (size_t)tk0 * H + c4 * 4;
    const float* ap1 = x + (size_t)tk1 * H + c4 * 4;
    const float* bp1 = w1 + ((size_t)e * F + n0 + br) * H + c4 * 4;
    const float* bp3 = w3 + ((size_t)e * F + n0 + br) * H + c4 * 4;

    // ---- compute mapping ----
    const int lane = tid & 31, wid = tid >> 5;
    const int wm = (wid & 3) * 32, wn = (wid >> 2) * 32;
    const int g  = lane >> 2, tg = lane & 3;

    float acc1[2][4][4] = {}, acc3[2][4][4] = {};

    for (int k0 = 0; k0 < H; k0 += BK) {
        float4 av0 = *(const float4*)(ap0 + k0);
        float4 av1 = *(const float4*)(ap1 + k0);
        float4 bv1 = *(const float4*)(bp1 + k0);
        float4 bv3 = *(const float4*)(bp3 + k0);
        __syncthreads();
        *(uint4*)&As [ar0 * SP + c4 * 4] = f4_to_tf(av0);
        *(uint4*)&As [ar1 * SP + c4 * 4] = f4_to_tf(av1);
        *(uint4*)&Bs1[br  * SP + c4 * 4] = f4_to_tf(bv1);
        *(uint4*)&Bs3[br  * SP + c4 * 4] = f4_to_tf(bv3);
        __syncthreads();

#pragma unroll
        for (int kk = 0; kk < BK; kk += 8) {
            unsigned a[2][4];
#pragma unroll
            for (int mt = 0; mt < 2; mt++) {
                int mr = wm + mt * 16 + g;
                a[mt][0] = As[mr * SP + kk + tg];
                a[mt][1] = As[(mr + 8) * SP + kk + tg];
                a[mt][2] = As[mr * SP + kk + tg + 4];
                a[mt][3] = As[(mr + 8) * SP + kk + tg + 4];
            }
#pragma unroll
            for (int nt = 0; nt < 4; nt++) {
                int nr = wn + nt * 8 + g;
                unsigned b[2];
                b[0] = Bs1[nr * SP + kk + tg];
                b[1] = Bs1[nr * SP + kk + tg + 4];
                mma_tf32(acc1[0][nt], a[0], b);
                mma_tf32(acc1[1][nt], a[1], b);
                b[0] = Bs3[nr * SP + kk + tg];
                b[1] = Bs3[nr * SP + kk + tg + 4];
                mma_tf32(acc3[0][nt], a[0], b);
                mma_tf32(acc3[1][nt], a[1], b);
            }
        }
    }

    // ---- epilogue: SwiGLU, store to g_mid ----
#pragma unroll
    for (int mt = 0; mt < 2; mt++) {
#pragma unroll
        for (int half = 0; half < 2; half++) {
            int m = m0 + wm + mt * 16 + g + half * 8;
            if (m >= ne) continue;
            float* dst = g_mid + ((size_t)e * T + m) * F + n0 + wn;
#pragma unroll
            for (int nt = 0; nt < 4; nt++) {
                float h0 = acc1[mt][nt][half * 2 + 0];
                float h1 = acc1[mt][nt][half * 2 + 1];
                float g0 = acc3[mt][nt][half * 2 + 0];
                float g1 = acc3[mt][nt][half * 2 + 1];
                float2 v;
                v.x = h0 / (1.f + __expf(-h0)) * g0;
                v.y = h1 / (1.f + __expf(-h1)) * g1;
                *(float2*)(dst + nt * 8 + tg * 2) = v;
            }
        }
    }
}

// ---------------------------------------------------------------
// GEMM2 (tf32): out[tok] += weight * (mid . w2^T)
__global__ __launch_bounds__(256, 2) void gemm2_kernel(
    const float* __restrict__ w2,
    float* __restrict__ out)
{
    const int e  = blockIdx.z;
    const int n0 = blockIdx.x * BN;
    const int m0 = blockIdx.y * BM;
    const int ne = g_cnt[e];
    if (m0 >= ne) return;

    __shared__ unsigned As[BM * SP];
    __shared__ unsigned Bs[BN * SP];

    const int tid = threadIdx.x;
    const int c4  = tid & 3;
    const int ar0 = tid >> 2;
    const int ar1 = ar0 + 64;
    const int br  = tid >> 2;

    const float* ap0 = g_mid + ((size_t)e * T + m0 + ar0) * F + c4 * 4;
    const float* ap1 = g_mid + ((size_t)e * T + m0 + ar1) * F + c4 * 4;
    const float* bp  = w2 + ((size_t)e * H + n0 + br) * F + c4 * 4;

    const int lane = tid & 31, wid = tid >> 5;
    const int wm = (wid & 3) * 32, wn = (wid >> 2) * 32;
    const int g  = lane >> 2, tg = lane & 3;

    float acc[2][4][4] = {};

    for (int k0 = 0; k0 < F; k0 += BK) {
        float4 av0 = *(const float4*)(ap0 + k0);
        float4 av1 = *(const float4*)(ap1 + k0);
        float4 bv  = *(const float4*)(bp + k0);
        __syncthreads();
        *(uint4*)&As[ar0 * SP + c4 * 4] = f4_to_tf(av0);
        *(uint4*)&As[ar1 * SP + c4 * 4] = f4_to_tf(av1);
        *(uint4*)&Bs[br  * SP + c4 * 4] = f4_to_tf(bv);
        __syncthreads();

#pragma unroll
        for (int kk = 0; kk < BK; kk += 8) {
            unsigned a[2][4];
#pragma unroll
            for (int mt = 0; mt < 2; mt++) {
                int mr = wm + mt * 16 + g;
                a[mt][0] = As[mr * SP + kk + tg];
                a[mt][1] = As[(mr + 8) * SP + kk + tg];
                a[mt][2] = As[mr * SP + kk + tg + 4];
                a[mt][3] = As[(mr + 8) * SP + kk + tg + 4];
            }
#pragma unroll
            for (int nt = 0; nt < 4; nt++) {
                int nr = wn + nt * 8 + g;
                unsigned b[2];
                b[0] = Bs[nr * SP + kk + tg];
                b[1] = Bs[nr * SP + kk + tg + 4];
                mma_tf32(acc[0][nt], a[0], b);
                mma_tf32(acc[1][nt], a[1], b);
            }
        }
    }

    // ---- epilogue: weighted atomic scatter into out ----
#pragma unroll
    for (int mt = 0; mt < 2; mt++) {
#pragma unroll
        for (int half = 0; half < 2; half++) {
            int m = m0 + wm + mt * 16 + g + half * 8;
            if (m >= ne) continue;
            int   tok = g_tok[e * T + m];
            float w   = g_wgt[e * T + m];
            float* dst = out + (size_t)tok * H + n0 + wn;
#pragma unroll
            for (int nt = 0; nt < 4; nt++) {
                atomicAdd(dst + nt * 8 + tg * 2 + 0, w * acc[mt][nt][half * 2 + 0]);
                atomicAdd(dst + nt * 8 + tg * 2 + 1, w * acc[mt][nt][half * 2 + 1]);
            }
        }
    }
}

// ---------------------------------------------------------------
extern "C" void kernel_launch(void* const* d_in, const int* in_sizes, int n_in,
                              void* d_out, int out_size)
{
    const float* x  = (const float*)d_in[0];   // [B,S,H] fp32
    const float* gw = (const float*)d_in[1];   // [E,H]
    const float* w1 = (const float*)d_in[2];   // [E,F,H]
    const float* w2 = (const float*)d_in[3];   // [E,H,F]
    const float* w3 = (const float*)d_in[4];   // [E,F,H]
    float* out = (float*)d_out;

    const size_t main_sz = (size_t)T * H;
    float* logits = ((size_t)out_size >= main_sz + (size_t)T * E)
                        ? out + main_sz : nullptr;

    cudaMemsetAsync(d_out, 0, (size_t)out_size * sizeof(float));
    zero_cnt_kernel<<<1, 32>>>();
    router_kernel<<<T, 128>>>(x, gw, logits);
    gemm1_kernel<<<dim3(F / BN, T / BM, E), 256>>>(x, w1, w3);
    gemm2_kernel<<<dim3(H / BN, T / BM, E), 256>>>(w2, out);
}

// round 4
// speedup vs baseline: 5.3725x; 1.8845x over previous
#include <cuda_runtime.h>
#include <cuda_fp16.h>
#include <math.h>

#define H 1024
#define F 2048
#define E 8
#define T 2048

#define BM 128
#define BN 64
#define BK 32
#define SPH 40   // smem row stride in halfs: banks (r*20)%32 all distinct -> ldmatrix conflict-free

// ---- scratch (device globals: allocation-free per harness rules) ----
__device__ int    g_cnt[E];
__device__ int    g_tok[E * T];
__device__ float  g_wgt[E * T];
__device__ __half g_mid[(size_t)E * T * F];   // [E][T][F] fp16 compacted per-expert rows

// ---------------------------------------------------------------
__device__ __forceinline__ void ldsm4(unsigned r[4], const __half* p) {
    unsigned a = (unsigned)__cvta_generic_to_shared(p);
    asm volatile("ldmatrix.sync.aligned.m8n8.x4.shared.b16 {%0,%1,%2,%3}, [%4];"
                 : "=r"(r[0]), "=r"(r[1]), "=r"(r[2]), "=r"(r[3]) : "r"(a));
}
__device__ __forceinline__ void mma16(float c[4], const unsigned a[4], unsigned b0, unsigned b1) {
    asm volatile(
        "mma.sync.aligned.m16n8k16.row.col.f32.f16.f16.f32 "
        "{%0,%1,%2,%3},{%4,%5,%6,%7},{%8,%9},{%0,%1,%2,%3};"
        : "+f"(c[0]), "+f"(c[1]), "+f"(c[2]), "+f"(c[3])
        : "r"(a[0]), "r"(a[1]), "r"(a[2]), "r"(a[3]), "r"(b0), "r"(b1));
}
__device__ __forceinline__ uint2 f4h(float4 v) {
    __half2 lo = __floats2half2_rn(v.x, v.y);
    __half2 hi = __floats2half2_rn(v.z, v.w);
    uint2 r;
    r.x = *(unsigned*)&lo; r.y = *(unsigned*)&hi;
    return r;
}

// ---------------------------------------------------------------
__global__ void zero_cnt_kernel() {
    if (threadIdx.x < E) g_cnt[threadIdx.x] = 0;
}

// ---------------------------------------------------------------
// Router: one warp per token. 256 blocks x 256 threads.
__global__ __launch_bounds__(256) void router_kernel(
    const float* __restrict__ x, const float* __restrict__ gw,
    float* __restrict__ logits_out)
{
    const int t    = blockIdx.x * 8 + (threadIdx.x >> 5);
    const int lane = threadIdx.x & 31;
    const float4* xr  = (const float4*)(x + (size_t)t * H);
    const float4* gw4 = (const float4*)gw;

    float acc[E];
#pragma unroll
    for (int e = 0; e < E; e++) acc[e] = 0.f;

#pragma unroll
    for (int i = 0; i < 8; i++) {
        float4 xv = xr[i * 32 + lane];
#pragma unroll
        for (int e = 0; e < E; e++) {
            float4 g = gw4[e * 256 + i * 32 + lane];
            acc[e] += xv.x * g.x + xv.y * g.y + xv.z * g.z + xv.w * g.w;
        }
    }
#pragma unroll
    for (int e = 0; e < E; e++) {
#pragma unroll
        for (int o = 16; o > 0; o >>= 1)
            acc[e] += __shfl_xor_sync(0xffffffffu, acc[e], o);
    }

    if (lane == 0) {
        if (logits_out) {
#pragma unroll
            for (int e = 0; e < E; e++) logits_out[(size_t)t * E + e] = acc[e];
        }
        int i1 = 0;
#pragma unroll
        for (int e = 1; e < E; e++) if (acc[e] > acc[i1]) i1 = e;
        int i2 = -1;
#pragma unroll
        for (int e = 0; e < E; e++) {
            if (e == i1) continue;
            if (i2 < 0 || acc[e] > acc[i2]) i2 = e;
        }
        float wa = 1.f / (1.f + expf(acc[i2] - acc[i1]));
        float wb = 1.f - wa;
        int s1 = atomicAdd(&g_cnt[i1], 1);
        g_tok[i1 * T + s1] = t; g_wgt[i1 * T + s1] = wa;
        int s2 = atomicAdd(&g_cnt[i2], 1);
        g_tok[i2 * T + s2] = t; g_wgt[i2 * T + s2] = wb;
    }
}

// ---------------------------------------------------------------
// GEMM1 (fp16 mma): mid = silu(x.w1^T) * (x.w3^T), gathered rows -> g_mid fp16.
__global__ __launch_bounds__(256, 2) void gemm1_kernel(
    const float* __restrict__ x,
    const float* __restrict__ w1,
    const float* __restrict__ w3)
{
    const int e  = blockIdx.z;
    const int n0 = blockIdx.x * BN;
    const int m0 = blockIdx.y * BM;
    const int ne = g_cnt[e];
    if (m0 >= ne) return;

    __shared__ __align__(16) __half sA [2][BM * SPH];
    __shared__ __align__(16) __half sB1[2][BN * SPH];
    __shared__ __align__(16) __half sB3[2][BN * SPH];

    const int tid  = threadIdx.x;
    const int lane = tid & 31, wid = tid >> 5;
    const int wm   = (wid & 3) * 32, wn = (wid >> 2) * 32;

    // loader mapping: A rows (tid>>3)+32r, col4=(tid&7); B rows (tid>>3)+32r
    const int lrow = tid >> 3, lc4 = tid & 7;

    const float* ap[4];
#pragma unroll
    for (int r = 0; r < 4; r++) {
        int m = m0 + lrow + 32 * r;
        int idx = (m < ne) ? m : (ne - 1);
        ap[r] = x + (size_t)g_tok[e * T + idx] * H + lc4 * 4;
    }
    const float* b1p[2];
    const float* b3p[2];
#pragma unroll
    for (int r = 0; r < 2; r++) {
        b1p[r] = w1 + ((size_t)e * F + n0 + lrow + 32 * r) * H + lc4 * 4;
        b3p[r] = w3 + ((size_t)e * F + n0 + lrow + 32 * r) * H + lc4 * 4;
    }

    float4 va[4], vb1[2], vb3[2];
    float acc1[2][4][4] = {}, acc3[2][4][4] = {};

    // prologue load + store
#pragma unroll
    for (int r = 0; r < 4; r++) va[r] = *(const float4*)(ap[r]);
#pragma unroll
    for (int r = 0; r < 2; r++) { vb1[r] = *(const float4*)(b1p[r]); vb3[r] = *(const float4*)(b3p[r]); }
#pragma unroll
    for (int r = 0; r < 4; r++) *(uint2*)&sA[0][(lrow + 32 * r) * SPH + lc4 * 4] = f4h(va[r]);
#pragma unroll
    for (int r = 0; r < 2; r++) {
        *(uint2*)&sB1[0][(lrow + 32 * r) * SPH + lc4 * 4] = f4h(vb1[r]);
        *(uint2*)&sB3[0][(lrow + 32 * r) * SPH + lc4 * 4] = f4h(vb3[r]);
    }
    __syncthreads();

    int cur = 0;
    for (int chunk = 1; chunk <= H / BK; chunk++) {
        if (chunk < H / BK) {
            int k0 = chunk * BK;
#pragma unroll
            for (int r = 0; r < 4; r++) va[r] = *(const float4*)(ap[r] + k0);
#pragma unroll
            for (int r = 0; r < 2; r++) { vb1[r] = *(const float4*)(b1p[r] + k0); vb3[r] = *(const float4*)(b3p[r] + k0); }
        }
        // compute on buffer cur
#pragma unroll
        for (int kk = 0; kk < BK; kk += 16) {
            unsigned a[2][4];
#pragma unroll
            for (int mt = 0; mt < 2; mt++)
                ldsm4(a[mt], &sA[cur][(wm + mt * 16 + (lane & 15)) * SPH + kk + (lane >> 4) * 8]);
            unsigned b1f[2][4], b3f[2][4];
#pragma unroll
            for (int bh = 0; bh < 2; bh++) {
                int row = wn + bh * 16 + ((lane >> 4) & 1) * 8 + (lane & 7);
                int col = kk + ((lane >> 3) & 1) * 8;
                ldsm4(b1f[bh], &sB1[cur][row * SPH + col]);
                ldsm4(b3f[bh], &sB3[cur][row * SPH + col]);
            }
#pragma unroll
            for (int mt = 0; mt < 2; mt++)
#pragma unroll
                for (int nt = 0; nt < 4; nt++) {
                    int bh = nt >> 1, pr = (nt & 1) * 2;
                    mma16(acc1[mt][nt], a[mt], b1f[bh][pr], b1f[bh][pr + 1]);
                    mma16(acc3[mt][nt], a[mt], b3f[bh][pr], b3f[bh][pr + 1]);
                }
        }
        if (chunk < H / BK) {
            int nxt = cur ^ 1;
#pragma unroll
            for (int r = 0; r < 4; r++) *(uint2*)&sA[nxt][(lrow + 32 * r) * SPH + lc4 * 4] = f4h(va[r]);
#pragma unroll
            for (int r = 0; r < 2; r++) {
                *(uint2*)&sB1[nxt][(lrow + 32 * r) * SPH + lc4 * 4] = f4h(vb1[r]);
                *(uint2*)&sB3[nxt][(lrow + 32 * r) * SPH + lc4 * 4] = f4h(vb3[r]);
            }
            __syncthreads();
            cur = nxt;
        }
    }

    // epilogue: SwiGLU -> g_mid (fp16)
    const int g = lane >> 2, tg = lane & 3;
#pragma unroll
    for (int mt = 0; mt < 2; mt++)
#pragma unroll
        for (int half = 0; half < 2; half++) {
            int m = m0 + wm + mt * 16 + g + half * 8;
            if (m >= ne) continue;
            __half* dst = g_mid + ((size_t)e * T + m) * F + n0 + wn;
#pragma unroll
            for (int nt = 0; nt < 4; nt++) {
                float h0 = acc1[mt][nt][half * 2 + 0];
                float h1 = acc1[mt][nt][half * 2 + 1];
                float g0 = acc3[mt][nt][half * 2 + 0];
                float g1 = acc3[mt][nt][half * 2 + 1];
                float r0 = h0 / (1.f + __expf(-h0)) * g0;
                float r1 = h1 / (1.f + __expf(-h1)) * g1;
                __half2 v = __floats2half2_rn(r0, r1);
                *(__half2*)(dst + nt * 8 + tg * 2) = v;
            }
        }
}

// ---------------------------------------------------------------
// GEMM2 (fp16 mma): out[tok] += weight * (mid . w2^T). A is fp16 in g_mid.
__global__ __launch_bounds__(256, 2) void gemm2_kernel(
    const float* __restrict__ w2,
    float* __restrict__ out)
{
    const int e  = blockIdx.z;
    const int n0 = blockIdx.x * BN;
    const int m0 = blockIdx.y * BM;
    const int ne = g_cnt[e];
    if (m0 >= ne) return;

    __shared__ __align__(16) __half sA[2][BM * SPH];
    __shared__ __align__(16) __half sB[2][BN * SPH];

    const int tid  = threadIdx.x;
    const int lane = tid & 31, wid = tid >> 5;
    const int wm   = (wid & 3) * 32, wn = (wid >> 2) * 32;

    // A loader: fp16 uint4 (8 halfs). row=(tid>>2)+64r, colh=(tid&3)*8
    const int arow = tid >> 2, ac8 = tid & 3;
    const __half* amp[2];
#pragma unroll
    for (int r = 0; r < 2; r++)
        amp[r] = g_mid + ((size_t)e * T + m0 + arow + 64 * r) * F + ac8 * 8;

    // B loader: fp32 float4. row=(tid>>3)+32r, col4=(tid&7)
    const int brow = tid >> 3, bc4 = tid & 7;
    const float* bp[2];
#pragma unroll
    for (int r = 0; r < 2; r++)
        bp[r] = w2 + ((size_t)e * H + n0 + brow + 32 * r) * F + bc4 * 4;

    uint4  vA[2];
    float4 vB[2];
    float acc[2][4][4] = {};

#pragma unroll
    for (int r = 0; r < 2; r++) { vA[r] = *(const uint4*)(amp[r]); vB[r] = *(const float4*)(bp[r]); }
#pragma unroll
    for (int r = 0; r < 2; r++) {
        *(uint4*)&sA[0][(arow + 64 * r) * SPH + ac8 * 8] = vA[r];
        *(uint2*)&sB[0][(brow + 32 * r) * SPH + bc4 * 4] = f4h(vB[r]);
    }
    __syncthreads();

    int cur = 0;
    for (int chunk = 1; chunk <= F / BK; chunk++) {
        if (chunk < F / BK) {
            int k0 = chunk * BK;
#pragma unroll
            for (int r = 0; r < 2; r++) { vA[r] = *(const uint4*)(amp[r] + k0); vB[r] = *(const float4*)(bp[r] + k0); }
        }
#pragma unroll
        for (int kk = 0; kk < BK; kk += 16) {
            unsigned a[2][4];
#pragma unroll
            for (int mt = 0; mt < 2; mt++)
                ldsm4(a[mt], &sA[cur][(wm + mt * 16 + (lane & 15)) * SPH + kk + (lane >> 4) * 8]);
            unsigned bf[2][4];
#pragma unroll
            for (int bh = 0; bh < 2; bh++) {
                int row = wn + bh * 16 + ((lane >> 4) & 1) * 8 + (lane & 7);
                int col = kk + ((lane >> 3) & 1) * 8;
                ldsm4(bf[bh], &sB[cur][row * SPH + col]);
            }
#pragma unroll
            for (int mt = 0; mt < 2; mt++)
#pragma unroll
                for (int nt = 0; nt < 4; nt++) {
                    int bh = nt >> 1, pr = (nt & 1) * 2;
                    mma16(acc[mt][nt], a[mt], bf[bh][pr], bf[bh][pr + 1]);
                }
        }
        if (chunk < F / BK) {
            int nxt = cur ^ 1;
#pragma unroll
            for (int r = 0; r < 2; r++) {
                *(uint4*)&sA[nxt][(arow + 64 * r) * SPH + ac8 * 8] = vA[r];
                *(uint2*)&sB[nxt][(brow + 32 * r) * SPH + bc4 * 4] = f4h(vB[r]);
            }
            __syncthreads();
            cur = nxt;
        }
    }

    // epilogue: weighted atomic scatter
    const int g = lane >> 2, tg = lane & 3;
#pragma unroll
    for (int mt = 0; mt < 2; mt++)
#pragma unroll
        for (int half = 0; half < 2; half++) {
            int m = m0 + wm + mt * 16 + g + half * 8;
            if (m >= ne) continue;
            int   tok = g_tok[e * T + m];
            float w   = g_wgt[e * T + m];
            float* dst = out + (size_t)tok * H + n0 + wn;
#pragma unroll
            for (int nt = 0; nt < 4; nt++) {
                atomicAdd(dst + nt * 8 + tg * 2 + 0, w * acc[mt][nt][half * 2 + 0]);
                atomicAdd(dst + nt * 8 + tg * 2 + 1, w * acc[mt][nt][half * 2 + 1]);
            }
        }
}

// ---------------------------------------------------------------
extern "C" void kernel_launch(void* const* d_in, const int* in_sizes, int n_in,
                              void* d_out, int out_size)
{
    const float* x  = (const float*)d_in[0];
    const float* gw = (const float*)d_in[1];
    const float* w1 = (const float*)d_in[2];
    const float* w2 = (const float*)d_in[3];
    const float* w3 = (const float*)d_in[4];
    float* out = (float*)d_out;

    const size_t main_sz = (size_t)T * H;
    float* logits = ((size_t)out_size >= main_sz + (size_t)T * E)
                        ? out + main_sz : nullptr;

    cudaMemsetAsync(d_out, 0, (size_t)out_size * sizeof(float));
    zero_cnt_kernel<<<1, 32>>>();
    router_kernel<<<T / 8, 256>>>(x, gw, logits);
    gemm1_kernel<<<dim3(F / BN, T / BM, E), 256>>>(x, w1, w3);
    gemm2_kernel<<<dim3(H / BN, T / BM, E), 256>>>(w2, out);
}

// round 6
// speedup vs baseline: 6.6441x; 1.2367x over previous
#include <cuda_runtime.h>
#include <cuda_fp16.h>
#include <math.h>
#include <stdint.h>

#define H 1024
#define F 2048
#define E 8
#define T 2048

// ---- gemm1 tiles (unchanged from R4) ----
#define BM 128
#define BN 64
#define BK 32
#define SPH 40   // smem row stride in halfs; (20r)%32 distinct over r=0..7 -> ldmatrix conflict-free

// ---- gemm2 tiles (R6) ----
#define BM2 128
#define BN2 128
#define BK2 32

// ---- scratch (device globals: allocation-free per harness rules) ----
__device__ int    g_cnt[E];
__device__ int    g_tok[E * T];
__device__ float  g_wgt[E * T];
__device__ __half g_mid[(size_t)E * T * F];   // [E][T][F] fp16 compacted per-expert rows

// ---------------------------------------------------------------
__device__ __forceinline__ void ldsm4(unsigned r[4], const __half* p) {
    unsigned a = (unsigned)__cvta_generic_to_shared(p);
    asm volatile("ldmatrix.sync.aligned.m8n8.x4.shared.b16 {%0,%1,%2,%3}, [%4];"
                 : "=r"(r[0]), "=r"(r[1]), "=r"(r[2]), "=r"(r[3]) : "r"(a));
}
__device__ __forceinline__ void mma16(float c[4], const unsigned a[4], unsigned b0, unsigned b1) {
    asm volatile(
        "mma.sync.aligned.m16n8k16.row.col.f32.f16.f16.f32 "
        "{%0,%1,%2,%3},{%4,%5,%6,%7},{%8,%9},{%0,%1,%2,%3};"
        : "+f"(c[0]), "+f"(c[1]), "+f"(c[2]), "+f"(c[3])
        : "r"(a[0]), "r"(a[1]), "r"(a[2]), "r"(a[3]), "r"(b0), "r"(b1));
}
__device__ __forceinline__ uint2 f4h(float4 v) {
    __half2 lo = __floats2half2_rn(v.x, v.y);
    __half2 hi = __floats2half2_rn(v.z, v.w);
    uint2 r;
    r.x = *(unsigned*)&lo; r.y = *(unsigned*)&hi;
    return r;
}
__device__ __forceinline__ void cp_async16(const __half* sdst, const __half* gsrc) {
    unsigned d = (unsigned)__cvta_generic_to_shared(sdst);
    asm volatile("cp.async.cg.shared.global [%0], [%1], 16;" :: "r"(d), "l"(gsrc));
}
#define CP_COMMIT() asm volatile("cp.async.commit_group;" ::: "memory")
#define CP_WAIT0()  asm volatile("cp.async.wait_group 0;" ::: "memory")

// ---------------------------------------------------------------
__global__ void zero_cnt_kernel() {
    if (threadIdx.x < E) g_cnt[threadIdx.x] = 0;
}

// ---------------------------------------------------------------
// Router: one warp per token. 256 blocks x 256 threads.
__global__ __launch_bounds__(256) void router_kernel(
    const float* __restrict__ x, const float* __restrict__ gw,
    float* __restrict__ logits_out)
{
    const int t    = blockIdx.x * 8 + (threadIdx.x >> 5);
    const int lane = threadIdx.x & 31;
    const float4* xr  = (const float4*)(x + (size_t)t * H);
    const float4* gw4 = (const float4*)gw;

    float acc[E];
#pragma unroll
    for (int e = 0; e < E; e++) acc[e] = 0.f;

#pragma unroll
    for (int i = 0; i < 8; i++) {
        float4 xv = xr[i * 32 + lane];
#pragma unroll
        for (int e = 0; e < E; e++) {
            float4 g = gw4[e * 256 + i * 32 + lane];
            acc[e] += xv.x * g.x + xv.y * g.y + xv.z * g.z + xv.w * g.w;
        }
    }
#pragma unroll
    for (int e = 0; e < E; e++)
#pragma unroll
        for (int o = 16; o > 0; o >>= 1)
            acc[e] += __shfl_xor_sync(0xffffffffu, acc[e], o);

    if (lane == 0) {
        if (logits_out)
#pragma unroll
            for (int e = 0; e < E; e++) logits_out[(size_t)t * E + e] = acc[e];
        int i1 = 0;
#pragma unroll
        for (int e = 1; e < E; e++) if (acc[e] > acc[i1]) i1 = e;
        int i2 = -1;
#pragma unroll
        for (int e = 0; e < E; e++) {
            if (e == i1) continue;
            if (i2 < 0 || acc[e] > acc[i2]) i2 = e;
        }
        float wa = 1.f / (1.f + expf(acc[i2] - acc[i1]));
        float wb = 1.f - wa;
        int s1 = atomicAdd(&g_cnt[i1], 1);
        g_tok[i1 * T + s1] = t; g_wgt[i1 * T + s1] = wa;
        int s2 = atomicAdd(&g_cnt[i2], 1);
        g_tok[i2 * T + s2] = t; g_wgt[i2 * T + s2] = wb;
    }
}

// ---------------------------------------------------------------
// GEMM1 (fp16 mma): mid = silu(x.w1^T) * (x.w3^T), gathered rows -> g_mid fp16.
// (unchanged from R4)
__global__ __launch_bounds__(256, 2) void gemm1_kernel(
    const float* __restrict__ x,
    const float* __restrict__ w1,
    const float* __restrict__ w3)
{
    const int e  = blockIdx.z;
    const int n0 = blockIdx.x * BN;
    const int m0 = blockIdx.y * BM;
    const int ne = g_cnt[e];
    if (m0 >= ne) return;

    __shared__ __align__(16) __half sA [2][BM * SPH];
    __shared__ __align__(16) __half sB1[2][BN * SPH];
    __shared__ __align__(16) __half sB3[2][BN * SPH];

    const int tid  = threadIdx.x;
    const int lane = tid & 31, wid = tid >> 5;
    const int wm   = (wid & 3) * 32, wn = (wid >> 2) * 32;

    const int lrow = tid >> 3, lc4 = tid & 7;

    const float* ap[4];
#pragma unroll
    for (int r = 0; r < 4; r++) {
        int m = m0 + lrow + 32 * r;
        int idx = (m < ne) ? m : (ne - 1);
        ap[r] = x + (size_t)g_tok[e * T + idx] * H + lc4 * 4;
    }
    const float* b1p[2];
    const float* b3p[2];
#pragma unroll
    for (int r = 0; r < 2; r++) {
        b1p[r] = w1 + ((size_t)e * F + n0 + lrow + 32 * r) * H + lc4 * 4;
        b3p[r] = w3 + ((size_t)e * F + n0 + lrow + 32 * r) * H + lc4 * 4;
    }

    float4 va[4], vb1[2], vb3[2];
    float acc1[2][4][4] = {}, acc3[2][4][4] = {};

#pragma unroll
    for (int r = 0; r < 4; r++) va[r] = *(const float4*)(ap[r]);
#pragma unroll
    for (int r = 0; r < 2; r++) { vb1[r] = *(const float4*)(b1p[r]); vb3[r] = *(const float4*)(b3p[r]); }
#pragma unroll
    for (int r = 0; r < 4; r++) *(uint2*)&sA[0][(lrow + 32 * r) * SPH + lc4 * 4] = f4h(va[r]);
#pragma unroll
    for (int r = 0; r < 2; r++) {
        *(uint2*)&sB1[0][(lrow + 32 * r) * SPH + lc4 * 4] = f4h(vb1[r]);
        *(uint2*)&sB3[0][(lrow + 32 * r) * SPH + lc4 * 4] = f4h(vb3[r]);
    }
    __syncthreads();

    int cur = 0;
    for (int chunk = 1; chunk <= H / BK; chunk++) {
        if (chunk < H / BK) {
            int k0 = chunk * BK;
#pragma unroll
            for (int r = 0; r < 4; r++) va[r] = *(const float4*)(ap[r] + k0);
#pragma unroll
            for (int r = 0; r < 2; r++) { vb1[r] = *(const float4*)(b1p[r] + k0); vb3[r] = *(const float4*)(b3p[r] + k0); }
        }
#pragma unroll
        for (int kk = 0; kk < BK; kk += 16) {
            unsigned a[2][4];
#pragma unroll
            for (int mt = 0; mt < 2; mt++)
                ldsm4(a[mt], &sA[cur][(wm + mt * 16 + (lane & 15)) * SPH + kk + (lane >> 4) * 8]);
            unsigned b1f[2][4], b3f[2][4];
#pragma unroll
            for (int bh = 0; bh < 2; bh++) {
                int row = wn + bh * 16 + ((lane >> 4) & 1) * 8 + (lane & 7);
                int col = kk + ((lane >> 3) & 1) * 8;
                ldsm4(b1f[bh], &sB1[cur][row * SPH + col]);
                ldsm4(b3f[bh], &sB3[cur][row * SPH + col]);
            }
#pragma unroll
            for (int mt = 0; mt < 2; mt++)
#pragma unroll
                for (int nt = 0; nt < 4; nt++) {
                    int bh = nt >> 1, pr = (nt & 1) * 2;
                    mma16(acc1[mt][nt], a[mt], b1f[bh][pr], b1f[bh][pr + 1]);
                    mma16(acc3[mt][nt], a[mt], b3f[bh][pr], b3f[bh][pr + 1]);
                }
        }
        if (chunk < H / BK) {
            int nxt = cur ^ 1;
#pragma unroll
            for (int r = 0; r < 4; r++) *(uint2*)&sA[nxt][(lrow + 32 * r) * SPH + lc4 * 4] = f4h(va[r]);
#pragma unroll
            for (int r = 0; r < 2; r++) {
                *(uint2*)&sB1[nxt][(lrow + 32 * r) * SPH + lc4 * 4] = f4h(vb1[r]);
                *(uint2*)&sB3[nxt][(lrow + 32 * r) * SPH + lc4 * 4] = f4h(vb3[r]);
            }
            __syncthreads();
            cur = nxt;
        }
    }

    const int g = lane >> 2, tg = lane & 3;
#pragma unroll
    for (int mt = 0; mt < 2; mt++)
#pragma unroll
        for (int half = 0; half < 2; half++) {
            int m = m0 + wm + mt * 16 + g + half * 8;
            if (m >= ne) continue;
            __half* dst = g_mid + ((size_t)e * T + m) * F + n0 + wn;
#pragma unroll
            for (int nt = 0; nt < 4; nt++) {
                float h0 = acc1[mt][nt][half * 2 + 0];
                float h1 = acc1[mt][nt][half * 2 + 1];
                float g0 = acc3[mt][nt][half * 2 + 0];
                float g1 = acc3[mt][nt][half * 2 + 1];
                float r0 = h0 / (1.f + __expf(-h0)) * g0;
                float r1 = h1 / (1.f + __expf(-h1)) * g1;
                __half2 v = __floats2half2_rn(r0, r1);
                *(__half2*)(dst + nt * 8 + tg * 2) = v;
            }
        }
}

// ---------------------------------------------------------------
// GEMM2 (fp16 mma, R6): block 128x128, warp tile 32x64, cp.async A stream.
// out[tok] += weight * (mid . w2^T)
__global__ __launch_bounds__(256, 2) void gemm2_kernel(
    const float* __restrict__ w2,
    float* __restrict__ out)
{
    const int e  = blockIdx.z;
    const int n0 = blockIdx.x * BN2;
    const int m0 = blockIdx.y * BM2;
    const int ne = g_cnt[e];
    if (m0 >= ne) return;

    __shared__ __align__(16) __half sA[2][BM2 * SPH];
    __shared__ __align__(16) __half sB[2][BN2 * SPH];

    const int tid  = threadIdx.x;
    const int lane = tid & 31, wid = tid >> 5;
    const int wm   = (wid & 3) * 32, wn = (wid >> 2) * 64;

    // A loader (cp.async): 512 granules of 16B; thread handles lin = i*256+tid
    //   row = lin>>2 (0..127), col8 = (lin&3)*8
    const __half* amb = g_mid + ((size_t)e * T + m0) * F;

    // B loader: 4 float4 per thread: row = (tid>>3) + 32r, col4 = (tid&7)*4
    const int brow = tid >> 3, bc4 = (tid & 7) * 4;
    const float* bp[4];
#pragma unroll
    for (int r = 0; r < 4; r++)
        bp[r] = w2 + ((size_t)e * H + n0 + brow + 32 * r) * F + bc4;

    float acc[2][8][4] = {};
    float4 vB[4];

    // ---- prologue: fill stage 0 ----
#pragma unroll
    for (int i = 0; i < 2; i++) {
        int lin = i * 256 + tid;
        int row = lin >> 2, col8 = (lin & 3) * 8;
        cp_async16(&sA[0][row * SPH + col8], amb + (size_t)row * F + col8);
    }
    CP_COMMIT();
#pragma unroll
    for (int r = 0; r < 4; r++) {
        vB[r] = *(const float4*)(bp[r]);
        *(uint2*)&sB[0][(brow + 32 * r) * SPH + bc4] = f4h(vB[r]);
    }
    CP_WAIT0();
    __syncthreads();

    const int NC = F / BK2;   // 64
    int cur = 0;
    for (int c = 0; c < NC; c++) {
        const int nxt = cur ^ 1;
        const bool more = (c + 1 < NC);
        if (more) {
            int k0 = (c + 1) * BK2;
#pragma unroll
            for (int i = 0; i < 2; i++) {
                int lin = i * 256 + tid;
                int row = lin >> 2, col8 = (lin & 3) * 8;
                cp_async16(&sA[nxt][row * SPH + col8], amb + (size_t)row * F + k0 + col8);
            }
            CP_COMMIT();
#pragma unroll
            for (int r = 0; r < 4; r++) vB[r] = *(const float4*)(bp[r] + k0);
        }

        // ---- compute on cur ----
#pragma unroll
        for (int kk = 0; kk < BK2; kk += 16) {
            unsigned a[2][4];
#pragma unroll
            for (int mt = 0; mt < 2; mt++)
                ldsm4(a[mt], &sA[cur][(wm + mt * 16 + (lane & 15)) * SPH + kk + (lane >> 4) * 8]);
            unsigned bf[4][4];
#pragma unroll
            for (int bh = 0; bh < 4; bh++) {
                int row = wn + bh * 16 + ((lane >> 4) & 1) * 8 + (lane & 7);
                int col = kk + ((lane >> 3) & 1) * 8;
                ldsm4(bf[bh], &sB[cur][row * SPH + col]);
            }
#pragma unroll
            for (int mt = 0; mt < 2; mt++)
#pragma unroll
                for (int nt = 0; nt < 8; nt++) {
                    int bh = nt >> 1, pr = (nt & 1) * 2;
                    mma16(acc[mt][nt], a[mt], bf[bh][pr], bf[bh][pr + 1]);
                }
        }

        if (more) {
#pragma unroll
            for (int r = 0; r < 4; r++)
                *(uint2*)&sB[nxt][(brow + 32 * r) * SPH + bc4] = f4h(vB[r]);
            CP_WAIT0();
            __syncthreads();
            cur = nxt;
        }
    }

    // ---- epilogue: weighted atomic scatter ----
    const int g = lane >> 2, tg = lane & 3;
#pragma unroll
    for (int mt = 0; mt < 2; mt++)
#pragma unroll
        for (int half = 0; half < 2; half++) {
            int m = m0 + wm + mt * 16 + g + half * 8;
            if (m >= ne) continue;
            int   tok = g_tok[e * T + m];
            float w   = g_wgt[e * T + m];
            float* dst = out + (size_t)tok * H + n0 + wn;
#pragma unroll
            for (int nt = 0; nt < 8; nt++) {
                atomicAdd(dst + nt * 8 + tg * 2 + 0, w * acc[mt][nt][half * 2 + 0]);
                atomicAdd(dst + nt * 8 + tg * 2 + 1, w * acc[mt][nt][half * 2 + 1]);
            }
        }
}

// ---------------------------------------------------------------
extern "C" void kernel_launch(void* const* d_in, const int* in_sizes, int n_in,
                              void* d_out, int out_size)
{
    const float* x  = (const float*)d_in[0];
    const float* gw = (const float*)d_in[1];
    const float* w1 = (const float*)d_in[2];
    const float* w2 = (const float*)d_in[3];
    const float* w3 = (const float*)d_in[4];
    float* out = (float*)d_out;

    const size_t main_sz = (size_t)T * H;
    float* logits = ((size_t)out_size >= main_sz + (size_t)T * E)
                        ? out + main_sz : nullptr;

    cudaMemsetAsync(d_out, 0, (size_t)out_size * sizeof(float));
    zero_cnt_kernel<<<1, 32>>>();
    router_kernel<<<T / 8, 256>>>(x, gw, logits);
    gemm1_kernel<<<dim3(F / BN, T / BM, E), 256>>>(x, w1, w3);
    gemm2_kernel<<<dim3(H / BN2, T / BM2, E), 256>>>(w2, out);
}